// round 13
// baseline (speedup 1.0000x reference)
#include <cuda_runtime.h>
#include <cuda_fp16.h>
#include <math.h>
#include <stdint.h>

// ---------------------------------------------------------------------------
// EquiConv v12: v11 + prologue/prefetch overlap + __expf silu.
//   k0_prepB : W2 -> g_B [18 chunks][128 n][64 k] fp16
//   k2_main  : pair-0 B prefetch issued at kernel entry (overlaps prologue);
//              prologue computes H into A smem tile + coefs into Cs using
//              pair-1 buffer as transient; mainloop = R7/R11 structure.
// ---------------------------------------------------------------------------

#define E_ROWS 65536
#define TILE_R 64
#define NCHUNK 18
#define NPAIR  9
#define ASTR   72                   // fp16 elems per A row (64 + 8)
#define BSTR   72                   // fp16 elems per B row (64 + 8)
#define A_BYTES (TILE_R*ASTR*2)     // 9216
#define CS_OFF  A_BYTES             // 9216
#define CS_BYTES (TILE_R*48*4)      // 12288
#define BS_OFF  (CS_OFF + CS_BYTES) // 21504
#define BBUF_B  (128*BSTR*2)        // 18432 (one chunk)
#define PAIR_B  (2*BBUF_B)          // 36864 (one pair buffer)
#define SMEM_TOTAL (BS_OFF + 2*PAIR_B)   // 95232

__device__ __align__(16) __half g_B[NCHUNK * 128 * 64];

// ------------------------------ asm helpers --------------------------------
__device__ __forceinline__ uint32_t smem_u32(const void* p) {
    uint32_t a;
    asm("{ .reg .u64 t; cvta.to.shared.u64 t, %1; cvt.u32.u64 %0, t; }" : "=r"(a) : "l"(p));
    return a;
}
#define LDSM4(r, a)                                                          \
    asm volatile("ldmatrix.sync.aligned.m8n8.x4.shared.b16 {%0,%1,%2,%3},[%4];" \
                 : "=r"((r)[0]), "=r"((r)[1]), "=r"((r)[2]), "=r"((r)[3]) : "r"(a))
#define MMA16816(d, a, b0, b1)                                               \
    asm volatile("mma.sync.aligned.m16n8k16.row.col.f32.f16.f16.f32 "        \
                 "{%0,%1,%2,%3},{%4,%5,%6,%7},{%8,%9},{%0,%1,%2,%3};"        \
                 : "+f"((d)[0]), "+f"((d)[1]), "+f"((d)[2]), "+f"((d)[3])    \
                 : "r"((a)[0]), "r"((a)[1]), "r"((a)[2]), "r"((a)[3]),       \
                   "r"(b0), "r"(b1))
#define CP_ASYNC16(d, s) \
    asm volatile("cp.async.cg.shared.global [%0], [%1], 16;" :: "r"(d), "l"(s))
#define CP_COMMIT()   asm volatile("cp.async.commit_group;" ::: "memory")
#define CP_WAIT1()    asm volatile("cp.async.wait_group 1;" ::: "memory")
#define CP_WAIT0()    asm volatile("cp.async.wait_group 0;" ::: "memory")

// stage one pair (2 chunks, 256 rows x 128B) into pair buffer (rows stride 144B)
__device__ __forceinline__ void stage_pair(int pair, uint32_t dst, int tid) {
    const char* src = (const char*)(g_B + pair * 2 * 128 * 64);
#pragma unroll
    for (int it = 0; it < 8; it++) {
        int t16 = tid + it * 256;          // 0..2047
        int row = t16 >> 3, c = t16 & 7;   // row 0..255
        CP_ASYNC16(dst + (uint32_t)(row >> 7) * BBUF_B + (row & 127) * 144 + c * 16,
                   src + row * 128 + c * 16);
    }
}

// ---------------------------------------------------------------------------
__global__ void k0_prepB(const float* __restrict__ W2) {
    int id = blockIdx.x * 256 + threadIdx.x;   // covers 2304*64 exactly
    int col = id >> 6, kk = id & 63;
    int chunk = col >> 7, n = col & 127;
    g_B[(chunk * 128 + n) * 64 + kk] = __float2half(W2[kk * 2304 + col]);
}

// ---------------------------------------------------------------------------
// contraction of one chunk's acc (j = 0..7, cols = cg*64 + j*8 + q2 + {0,1})
__device__ __forceinline__ void contract_chunk(
    int m, const float acc[8][4], float* o0, float* sA, float* qA,
    int rbase, int lrow0, int cg,
    const float* __restrict__ Cs, const float* __restrict__ fea_in1)
{
    if (m < 12) {
        const int ubase = (m < 8 ? m * 4 : 32 + (m - 8) * 4) + cg * 2;
#pragma unroll
        for (int rh = 0; rh < 2; rh++) {
            const int lrow = lrow0 + rh * 8;
            const float c0v = Cs[lrow * 48 + ubase];
            const float c1v = Cs[lrow * 48 + ubase + 1];
#pragma unroll
            for (int j = 0; j < 8; j++) {
                const float c = (j < 4) ? c0v : c1v;
                const int s = (rh * 4 + (j & 3)) * 2;
                o0[s]     = fmaf(c, acc[j][rh * 2],     o0[s]);
                o0[s + 1] = fmaf(c, acc[j][rh * 2 + 1], o0[s + 1]);
            }
        }
    } else if (m < 16) {
        const int u0 = (m - 12) * 8 + cg * 4;
#pragma unroll
        for (int rh = 0; rh < 2; rh++) {
            const int row = rbase + rh * 8;
            const float* xr = fea_in1 + row * 80 + u0;
#pragma unroll
            for (int j = 0; j < 8; j++) {
                const float cu = xr[j >> 1];
                const int s = rh * 4 + (j & 1) * 2;
                sA[s]     = fmaf(cu, acc[j][rh * 2],     sA[s]);
                sA[s + 1] = fmaf(cu, acc[j][rh * 2 + 1], sA[s + 1]);
            }
        }
    } else {
        const int u0 = (m - 16) * 8 + cg * 4;
#pragma unroll
        for (int rh = 0; rh < 2; rh++) {
            const int row = rbase + rh * 8;
            const float* xr = fea_in1 + row * 80 + 32 + 3 * u0;
#pragma unroll
            for (int j = 0; j < 8; j++) {
                const int s = (rh * 4 + (j & 1) * 2) * 3;
#pragma unroll
                for (int k = 0; k < 3; k++) {
                    const float cu = xr[3 * (j >> 1) + k];
                    qA[s + k]     = fmaf(cu, acc[j][rh * 2],     qA[s + k]);
                    qA[s + 3 + k] = fmaf(cu, acc[j][rh * 2 + 1], qA[s + 3 + k]);
                }
            }
        }
    }
}

// ---------------------------------------------------------------------------
__global__ __launch_bounds__(256, 2)
void k2_main(const float* __restrict__ fea_in1,
             const float* __restrict__ fea_in2,
             const float* __restrict__ fea_weight,
             const float* __restrict__ W1,
             float* __restrict__ out)
{
    extern __shared__ __align__(16) char smem[];
    const uint32_t sbase = smem_u32(smem);
    const int tid = threadIdx.x, wid = tid >> 5, lane = tid & 31;
    const int rg = wid >> 1, cg = wid & 1;
    const int r0 = blockIdx.x * TILE_R;

    __half* As = (__half*)smem;
    float*  Cs = (float*)(smem + CS_OFF);

    // ==== pair-0 B prefetch FIRST: overlaps the whole prologue ====
    stage_pair(0, sbase + BS_OFF, tid);            CP_COMMIT();

    // ==== fused prologue: H = 1.679*silu((fw@W1)/8)/8 -> As fp16; coefs -> Cs
    // transients live in the pair-1 buffer region (staged only after prologue)
    {
        float* W1s = (float*)(smem + BS_OFF + PAIR_B);           // 16KB
        float* fws = (float*)(smem + BS_OFF + PAIR_B + 16384);   // 16KB
        for (int idx = tid; idx < 64 * 64; idx += 256) W1s[idx] = W1[idx];
        for (int idx = tid; idx < 64 * 64; idx += 256) fws[idx] = fea_weight[r0 * 64 + idx];
        __syncthreads();

        const int rl = tid >> 3, l8 = tid & 7;           // rl 0..31
#pragma unroll 1
        for (int half = 0; half < 2; half++) {
            const int lrow = half * 32 + rl;
            float acc[8];
#pragma unroll
            for (int jj = 0; jj < 8; jj++) acc[jj] = 0.f;
#pragma unroll 8
            for (int k = 0; k < 64; k++) {
                const float fv = fws[lrow * 64 + k];
#pragma unroll
                for (int jj = 0; jj < 8; jj++) acc[jj] += fv * W1s[k * 64 + jj * 8 + l8];
            }
#pragma unroll
            for (int jj = 0; jj < 8; jj++) {
                const float z = acc[jj] * 0.125f;
                const float s = z / (1.f + __expf(-z));
                As[lrow * ASTR + jj * 8 + l8] = __float2half(1.679f * s * 0.125f);
            }
            // coefs for this row (8 lanes cooperate per row)
            const int grow = r0 + lrow;
            const float x20  = fea_in2[grow * 4 + 0];
            const float x21a = fea_in2[grow * 4 + 1];
            const float x21b = fea_in2[grow * 4 + 2];
            const float x21c = fea_in2[grow * 4 + 3];
            for (int u = l8; u < 32; u += 8)
                Cs[lrow * 48 + u] = 0.125f * x20 * fea_in1[grow * 80 + u];
            for (int u = l8; u < 16; u += 8) {
                const float* p = fea_in1 + grow * 80 + 32 + u * 3;
                const float b = p[0] * x21a + p[1] * x21b + p[2] * x21c;
                Cs[lrow * 48 + 32 + u] = 0.10206207261596575f * b;
            }
        }
        __syncthreads();   // As/Cs ready; W1s/fws dead -> pair-1 buffer reuse
    }

    // stage pair 1 (overwrites transient W1s/fws area)
    stage_pair(1, sbase + BS_OFF + PAIR_B, tid);   CP_COMMIT();

    // ldmatrix address groups + hoisted A fragments
    const int gp = lane >> 3, lr = lane & 7;
    const uint32_t aBase = sbase + (uint32_t)(((rg * 16 + 8 * (gp & 1) + lr) * ASTR
                                               + 8 * (gp >> 1)) * 2);
    uint32_t afrag[4][4];
#pragma unroll
    for (int ksb = 0; ksb < 4; ksb++)
        LDSM4(afrag[ksb], aBase + ksb * 32);

    uint32_t bOff[4];
#pragma unroll
    for (int p = 0; p < 4; p++)
        bOff[p] = (uint32_t)(((cg * 64 + 16 * p + 8 * (gp >> 1) + lr) * BSTR
                              + 8 * (gp & 1)) * 2);

    // persistent per-thread partial accumulators
    float o0[16], sA[8], qA[24];
#pragma unroll
    for (int i = 0; i < 16; i++) o0[i] = 0.f;
#pragma unroll
    for (int i = 0; i < 8; i++) sA[i] = 0.f;
#pragma unroll
    for (int i = 0; i < 24; i++) qA[i] = 0.f;

    const int rowq = lane >> 2;
    const int lrow0 = rg * 16 + rowq;          // local row (+ rh*8)
    const int rbase = r0 + lrow0;
    const int q2 = (lane & 3) * 2;

    float acc[8][4];

#pragma unroll 1
    for (int p = 0; p < NPAIR; p++) {
        if (p < NPAIR - 1) { CP_WAIT1(); } else { CP_WAIT0(); }
        __syncthreads();
        const uint32_t pbuf = sbase + BS_OFF + (uint32_t)(p & 1) * PAIR_B;

        // chunk 2p
#pragma unroll
        for (int j = 0; j < 8; j++)
#pragma unroll
            for (int c = 0; c < 4; c++) acc[j][c] = 0.f;
#pragma unroll
        for (int ksb = 0; ksb < 4; ksb++) {
#pragma unroll
            for (int pp = 0; pp < 4; pp++) {
                uint32_t r[4];
                LDSM4(r, pbuf + bOff[pp] + ksb * 32);
                MMA16816(acc[2 * pp],     afrag[ksb], r[0], r[1]);
                MMA16816(acc[2 * pp + 1], afrag[ksb], r[2], r[3]);
            }
        }
        contract_chunk(2 * p, acc, o0, sA, qA, rbase, lrow0, cg, Cs, fea_in1);

        // chunk 2p+1
#pragma unroll
        for (int j = 0; j < 8; j++)
#pragma unroll
            for (int c = 0; c < 4; c++) acc[j][c] = 0.f;
#pragma unroll
        for (int ksb = 0; ksb < 4; ksb++) {
#pragma unroll
            for (int pp = 0; pp < 4; pp++) {
                uint32_t r[4];
                LDSM4(r, pbuf + BBUF_B + bOff[pp] + ksb * 32);
                MMA16816(acc[2 * pp],     afrag[ksb], r[0], r[1]);
                MMA16816(acc[2 * pp + 1], afrag[ksb], r[2], r[3]);
            }
        }
        __syncthreads();                      // all B reads of this pair done
        if (p + 2 < NPAIR) {                  // refill this pair buffer
            stage_pair(p + 2, pbuf, tid);
            CP_COMMIT();
        }
        contract_chunk(2 * p + 1, acc, o0, sA, qA, rbase, lrow0, cg, Cs, fea_in1);
    }

    // ---- cross-cg reduction (cg=1 partials -> cg=0), reuse B area ----
    float* red = (float*)(smem + BS_OFF);      // 128 thr * 48 f = 24576 B
    const int half_id = rg * 32 + lane;
    if (cg == 1) {
        float* dst = red + half_id * 48;
#pragma unroll
        for (int i = 0; i < 16; i++) dst[i] = o0[i];
#pragma unroll
        for (int i = 0; i < 8; i++) dst[16 + i] = sA[i];
#pragma unroll
        for (int i = 0; i < 24; i++) dst[24 + i] = qA[i];
    }
    __syncthreads();
    if (cg == 0) {
        const float* src = red + half_id * 48;
#pragma unroll
        for (int i = 0; i < 16; i++) o0[i] += src[i];
#pragma unroll
        for (int i = 0; i < 8; i++) sA[i] += src[16 + i];
#pragma unroll
        for (int i = 0; i < 24; i++) qA[i] += src[24 + i];

        // ---- epilogue ----
        const float c011 = 0.125f;                 // pw011/sqrt(3)
        const float c101 = 0.17677669529663687f;   // pw101/sqrt(3)
#pragma unroll
        for (int rh = 0; rh < 2; rh++) {
            const int row = rbase + rh * 8;
            float* orow = out + row * 80;
            const int s = rh * 4;
#pragma unroll
            for (int jm = 0; jm < 4; jm++) {
                orow[8 * jm + q2]     = o0[(s + jm) * 2];
                orow[8 * jm + q2 + 1] = o0[(s + jm) * 2 + 1];
            }
            const float x20  = fea_in2[row * 4 + 0];
            const float x21a = fea_in2[row * 4 + 1];
            const float x21b = fea_in2[row * 4 + 2];
            const float x21c = fea_in2[row * 4 + 3];
#pragma unroll
            for (int slot = 0; slot < 4; slot++) {
                const int w = 8 * (slot >> 1) + q2 + (slot & 1);
                const float sv = sA[s + slot];
                orow[32 + 3 * w + 0] = c011 * x21a * sv + c101 * x20 * qA[(s + slot) * 3 + 0];
                orow[32 + 3 * w + 1] = c011 * x21b * sv + c101 * x20 * qA[(s + slot) * 3 + 1];
                orow[32 + 3 * w + 2] = c011 * x21c * sv + c101 * x20 * qA[(s + slot) * 3 + 2];
            }
        }
    }
}

// ---------------------------------------------------------------------------
extern "C" void kernel_launch(void* const* d_in, const int* in_sizes, int n_in,
                              void* d_out, int out_size)
{
    const float* fea_in1    = (const float*)d_in[0];
    const float* fea_in2    = (const float*)d_in[1];
    const float* fea_weight = (const float*)d_in[2];
    const float* W1         = (const float*)d_in[3];
    const float* W2         = (const float*)d_in[4];
    float* out = (float*)d_out;

    cudaFuncSetAttribute(k2_main, cudaFuncAttributeMaxDynamicSharedMemorySize, SMEM_TOTAL);

    k0_prepB<<<576, 256>>>(W2);
    k2_main<<<E_ROWS / TILE_R, 256, SMEM_TOTAL>>>(fea_in1, fea_in2, fea_weight, W1, out);
}

// round 14
// speedup vs baseline: 1.3726x; 1.3726x over previous
#include <cuda_runtime.h>
#include <cuda_fp16.h>
#include <math.h>
#include <stdint.h>

// ---------------------------------------------------------------------------
// EquiConv v13: tensor-core prologue.
//   k0_prepB : W2 -> g_B chunks (fp16)  +  W1^T -> g_W1f (fp16, B-layout)
//   k2_main  : per 64-row CTA:
//              prologue: fw -> fp16 A-tile, z = fw@W1 via 16 mma/warp,
//                        H = 1.679*silu(z/8)/8 -> As ; coefs -> Cs.
//              mainloop: R7/R11 structure (9 pairs, cp.async double buffer,
//              hoisted A frags, fragment-local contraction, cg-reduction).
// ---------------------------------------------------------------------------

#define E_ROWS 65536
#define TILE_R 64
#define NCHUNK 18
#define NPAIR  9
#define ASTR   72                   // fp16 elems per A row (64 + 8)
#define BSTR   72                   // fp16 elems per B row (64 + 8)
#define A_BYTES (TILE_R*ASTR*2)     // 9216
#define CS_OFF  A_BYTES             // 9216
#define CS_BYTES (TILE_R*48*4)      // 12288
#define BS_OFF  (CS_OFF + CS_BYTES) // 21504
#define BBUF_B  (128*BSTR*2)        // 18432 (one chunk)
#define PAIR_B  (2*BBUF_B)          // 36864 (one pair buffer)
#define SMEM_TOTAL (BS_OFF + 2*PAIR_B)   // 95232

__device__ __align__(16) __half g_B[NCHUNK * 128 * 64];
__device__ __align__(16) __half g_W1f[64 * 64];   // W1f[j][k] = W1[k][j]

// ------------------------------ asm helpers --------------------------------
__device__ __forceinline__ uint32_t smem_u32(const void* p) {
    uint32_t a;
    asm("{ .reg .u64 t; cvta.to.shared.u64 t, %1; cvt.u32.u64 %0, t; }" : "=r"(a) : "l"(p));
    return a;
}
#define LDSM4(r, a)                                                          \
    asm volatile("ldmatrix.sync.aligned.m8n8.x4.shared.b16 {%0,%1,%2,%3},[%4];" \
                 : "=r"((r)[0]), "=r"((r)[1]), "=r"((r)[2]), "=r"((r)[3]) : "r"(a))
#define MMA16816(d, a, b0, b1)                                               \
    asm volatile("mma.sync.aligned.m16n8k16.row.col.f32.f16.f16.f32 "        \
                 "{%0,%1,%2,%3},{%4,%5,%6,%7},{%8,%9},{%0,%1,%2,%3};"        \
                 : "+f"((d)[0]), "+f"((d)[1]), "+f"((d)[2]), "+f"((d)[3])    \
                 : "r"((a)[0]), "r"((a)[1]), "r"((a)[2]), "r"((a)[3]),       \
                   "r"(b0), "r"(b1))
#define CP_ASYNC16(d, s) \
    asm volatile("cp.async.cg.shared.global [%0], [%1], 16;" :: "r"(d), "l"(s))
#define CP_COMMIT()   asm volatile("cp.async.commit_group;" ::: "memory")
#define CP_WAIT1()    asm volatile("cp.async.wait_group 1;" ::: "memory")
#define CP_WAIT0()    asm volatile("cp.async.wait_group 0;" ::: "memory")

// stage one pair (2 chunks, 256 rows x 128B) into pair buffer (rows stride 144B)
__device__ __forceinline__ void stage_pair(int pair, uint32_t dst, int tid) {
    const char* src = (const char*)(g_B + pair * 2 * 128 * 64);
#pragma unroll
    for (int it = 0; it < 8; it++) {
        int t16 = tid + it * 256;          // 0..2047
        int row = t16 >> 3, c = t16 & 7;   // row 0..255
        CP_ASYNC16(dst + (uint32_t)(row >> 7) * BBUF_B + (row & 127) * 144 + c * 16,
                   src + row * 128 + c * 16);
    }
}

// stage W1f (64 rows x 128B) into smem rows of stride 144B
__device__ __forceinline__ void stage_W1f(uint32_t dst, int tid) {
    const char* src = (const char*)g_W1f;
#pragma unroll
    for (int it = 0; it < 2; it++) {
        int t16 = tid + it * 256;          // 0..511
        int row = t16 >> 3, c = t16 & 7;
        CP_ASYNC16(dst + row * 144 + c * 16, src + t16 * 16);
    }
}

// ---------------------------------------------------------------------------
__global__ void k0_prepB(const float* __restrict__ W2,
                         const float* __restrict__ W1) {
    int id = blockIdx.x * 256 + threadIdx.x;   // covers 2304*64 exactly
    int col = id >> 6, kk = id & 63;
    int chunk = col >> 7, n = col & 127;
    g_B[(chunk * 128 + n) * 64 + kk] = __float2half(W2[kk * 2304 + col]);
    if (id < 4096) {                            // W1f[j][k] = W1[k][j]
        int j = id >> 6, k = id & 63;
        g_W1f[j * 64 + k] = __float2half(W1[k * 64 + j]);
    }
}

// ---------------------------------------------------------------------------
// contraction of one chunk's acc (j = 0..7, cols = cg*64 + j*8 + q2 + {0,1})
__device__ __forceinline__ void contract_chunk(
    int m, const float acc[8][4], float* o0, float* sA, float* qA,
    int rbase, int lrow0, int cg,
    const float* __restrict__ Cs, const float* __restrict__ fea_in1)
{
    if (m < 12) {
        const int ubase = (m < 8 ? m * 4 : 32 + (m - 8) * 4) + cg * 2;
#pragma unroll
        for (int rh = 0; rh < 2; rh++) {
            const int lrow = lrow0 + rh * 8;
            const float c0v = Cs[lrow * 48 + ubase];
            const float c1v = Cs[lrow * 48 + ubase + 1];
#pragma unroll
            for (int j = 0; j < 8; j++) {
                const float c = (j < 4) ? c0v : c1v;
                const int s = (rh * 4 + (j & 3)) * 2;
                o0[s]     = fmaf(c, acc[j][rh * 2],     o0[s]);
                o0[s + 1] = fmaf(c, acc[j][rh * 2 + 1], o0[s + 1]);
            }
        }
    } else if (m < 16) {
        const int u0 = (m - 12) * 8 + cg * 4;
#pragma unroll
        for (int rh = 0; rh < 2; rh++) {
            const int row = rbase + rh * 8;
            const float* xr = fea_in1 + row * 80 + u0;
#pragma unroll
            for (int j = 0; j < 8; j++) {
                const float cu = xr[j >> 1];
                const int s = rh * 4 + (j & 1) * 2;
                sA[s]     = fmaf(cu, acc[j][rh * 2],     sA[s]);
                sA[s + 1] = fmaf(cu, acc[j][rh * 2 + 1], sA[s + 1]);
            }
        }
    } else {
        const int u0 = (m - 16) * 8 + cg * 4;
#pragma unroll
        for (int rh = 0; rh < 2; rh++) {
            const int row = rbase + rh * 8;
            const float* xr = fea_in1 + row * 80 + 32 + 3 * u0;
#pragma unroll
            for (int j = 0; j < 8; j++) {
                const int s = (rh * 4 + (j & 1) * 2) * 3;
#pragma unroll
                for (int k = 0; k < 3; k++) {
                    const float cu = xr[3 * (j >> 1) + k];
                    qA[s + k]     = fmaf(cu, acc[j][rh * 2],     qA[s + k]);
                    qA[s + 3 + k] = fmaf(cu, acc[j][rh * 2 + 1], qA[s + 3 + k]);
                }
            }
        }
    }
}

// ---------------------------------------------------------------------------
__global__ __launch_bounds__(256, 2)
void k2_main(const float* __restrict__ fea_in1,
             const float* __restrict__ fea_in2,
             const float* __restrict__ fea_weight,
             float* __restrict__ out)
{
    extern __shared__ __align__(16) char smem[];
    const uint32_t sbase = smem_u32(smem);
    const int tid = threadIdx.x, wid = tid >> 5, lane = tid & 31;
    const int rg = wid >> 1, cg = wid & 1;
    const int r0 = blockIdx.x * TILE_R;

    __half* As = (__half*)smem;
    float*  Cs = (float*)(smem + CS_OFF);

    // transient prologue buffers in pair-1 region
    const uint32_t pb1  = sbase + BS_OFF + PAIR_B;
    __half* Afw = (__half*)(smem + BS_OFF + PAIR_B + 9216);

    // ==== entry prefetch: W1f first (group 0), then pair-0 (group 1) ====
    stage_W1f(pb1, tid);                 CP_COMMIT();
    stage_pair(0, sbase + BS_OFF, tid);  CP_COMMIT();

    // ==== fw -> Afw fp16 (A-tile layout, stride ASTR) ====
    for (int idx = tid; idx < 64 * 16; idx += 256) {
        const int row = idx >> 4, c4 = idx & 15;
        const float4 v = ((const float4*)(fea_weight + (r0 + row) * 64))[c4];
        *(__half2*)(Afw + row * ASTR + c4 * 4)     = __floats2half2_rn(v.x, v.y);
        *(__half2*)(Afw + row * ASTR + c4 * 4 + 2) = __floats2half2_rn(v.z, v.w);
    }
    // ==== coefs -> Cs (independent of GEMM) ====
    {
        const int rl = tid >> 3, l8 = tid & 7;
#pragma unroll
        for (int hf = 0; hf < 2; hf++) {
            const int lrow = hf * 32 + rl;
            const int grow = r0 + lrow;
            const float x20  = fea_in2[grow * 4 + 0];
            const float x21a = fea_in2[grow * 4 + 1];
            const float x21b = fea_in2[grow * 4 + 2];
            const float x21c = fea_in2[grow * 4 + 3];
            for (int u = l8; u < 32; u += 8)
                Cs[lrow * 48 + u] = 0.125f * x20 * fea_in1[grow * 80 + u];
            for (int u = l8; u < 16; u += 8) {
                const float* p = fea_in1 + grow * 80 + 32 + u * 3;
                const float b = p[0] * x21a + p[1] * x21b + p[2] * x21c;
                Cs[lrow * 48 + 32 + u] = 0.10206207261596575f * b;
            }
        }
    }
    CP_WAIT1();            // W1f landed (pair-0 may still fly)
    __syncthreads();

    // ==== prologue GEMM: z = fw @ W1 (M64 N64 K64), then silu -> As ====
    const int gp = lane >> 3, lr = lane & 7;
    const int rowq = lane >> 2;
    const int q2 = (lane & 3) * 2;
    {
        const uint32_t afwBase = sbase + (uint32_t)(BS_OFF + PAIR_B + 9216)
            + (uint32_t)(((rg * 16 + 8 * (gp & 1) + lr) * ASTR + 8 * (gp >> 1)) * 2);
        uint32_t bOffW[2];
#pragma unroll
        for (int pp = 0; pp < 2; pp++)
            bOffW[pp] = (uint32_t)(((cg * 32 + 16 * pp + 8 * (gp >> 1) + lr) * BSTR
                                    + 8 * (gp & 1)) * 2);
        float accP[4][4];
#pragma unroll
        for (int j = 0; j < 4; j++)
#pragma unroll
            for (int c = 0; c < 4; c++) accP[j][c] = 0.f;
#pragma unroll
        for (int ksb = 0; ksb < 4; ksb++) {
            uint32_t aw[4];
            LDSM4(aw, afwBase + ksb * 32);
#pragma unroll
            for (int pp = 0; pp < 2; pp++) {
                uint32_t r[4];
                LDSM4(r, pb1 + bOffW[pp] + ksb * 32);
                MMA16816(accP[2 * pp],     aw, r[0], r[1]);
                MMA16816(accP[2 * pp + 1], aw, r[2], r[3]);
            }
        }
        // silu epilogue -> As (H = 1.679*silu(z/8)/8)
#pragma unroll
        for (int jt = 0; jt < 4; jt++) {
#pragma unroll
            for (int rh = 0; rh < 2; rh++) {
                const int row = rg * 16 + rowq + 8 * rh;
                const int col = cg * 32 + jt * 8 + q2;
                const float z0 = accP[jt][rh * 2]     * 0.125f;
                const float z1 = accP[jt][rh * 2 + 1] * 0.125f;
                const float h0 = 1.679f * 0.125f * z0 / (1.f + __expf(-z0));
                const float h1 = 1.679f * 0.125f * z1 / (1.f + __expf(-z1));
                *(__half2*)(As + row * ASTR + col) = __floats2half2_rn(h0, h1);
            }
        }
    }
    __syncthreads();       // As complete; W1f/Afw dead -> pair-1 reuse

    // stage pair 1 (overwrites transient region)
    stage_pair(1, pb1, tid);   CP_COMMIT();

    // ldmatrix address groups + hoisted A fragments
    const uint32_t aBase = sbase + (uint32_t)(((rg * 16 + 8 * (gp & 1) + lr) * ASTR
                                               + 8 * (gp >> 1)) * 2);
    uint32_t afrag[4][4];
#pragma unroll
    for (int ksb = 0; ksb < 4; ksb++)
        LDSM4(afrag[ksb], aBase + ksb * 32);

    uint32_t bOff[4];
#pragma unroll
    for (int p = 0; p < 4; p++)
        bOff[p] = (uint32_t)(((cg * 64 + 16 * p + 8 * (gp >> 1) + lr) * BSTR
                              + 8 * (gp & 1)) * 2);

    // persistent per-thread partial accumulators
    float o0[16], sA[8], qA[24];
#pragma unroll
    for (int i = 0; i < 16; i++) o0[i] = 0.f;
#pragma unroll
    for (int i = 0; i < 8; i++) sA[i] = 0.f;
#pragma unroll
    for (int i = 0; i < 24; i++) qA[i] = 0.f;

    const int lrow0 = rg * 16 + rowq;          // local row (+ rh*8)
    const int rbase = r0 + lrow0;

    float acc[8][4];

#pragma unroll 1
    for (int p = 0; p < NPAIR; p++) {
        if (p < NPAIR - 1) { CP_WAIT1(); } else { CP_WAIT0(); }
        __syncthreads();
        const uint32_t pbuf = sbase + BS_OFF + (uint32_t)(p & 1) * PAIR_B;

        // chunk 2p
#pragma unroll
        for (int j = 0; j < 8; j++)
#pragma unroll
            for (int c = 0; c < 4; c++) acc[j][c] = 0.f;
#pragma unroll
        for (int ksb = 0; ksb < 4; ksb++) {
#pragma unroll
            for (int pp = 0; pp < 4; pp++) {
                uint32_t r[4];
                LDSM4(r, pbuf + bOff[pp] + ksb * 32);
                MMA16816(acc[2 * pp],     afrag[ksb], r[0], r[1]);
                MMA16816(acc[2 * pp + 1], afrag[ksb], r[2], r[3]);
            }
        }
        contract_chunk(2 * p, acc, o0, sA, qA, rbase, lrow0, cg, Cs, fea_in1);

        // chunk 2p+1
#pragma unroll
        for (int j = 0; j < 8; j++)
#pragma unroll
            for (int c = 0; c < 4; c++) acc[j][c] = 0.f;
#pragma unroll
        for (int ksb = 0; ksb < 4; ksb++) {
#pragma unroll
            for (int pp = 0; pp < 4; pp++) {
                uint32_t r[4];
                LDSM4(r, pbuf + BBUF_B + bOff[pp] + ksb * 32);
                MMA16816(acc[2 * pp],     afrag[ksb], r[0], r[1]);
                MMA16816(acc[2 * pp + 1], afrag[ksb], r[2], r[3]);
            }
        }
        __syncthreads();                      // all B reads of this pair done
        if (p + 2 < NPAIR) {                  // refill this pair buffer
            stage_pair(p + 2, pbuf, tid);
            CP_COMMIT();
        }
        contract_chunk(2 * p + 1, acc, o0, sA, qA, rbase, lrow0, cg, Cs, fea_in1);
    }

    // ---- cross-cg reduction (cg=1 partials -> cg=0), reuse B area ----
    float* red = (float*)(smem + BS_OFF);      // 128 thr * 48 f = 24576 B
    const int half_id = rg * 32 + lane;
    if (cg == 1) {
        float* dst = red + half_id * 48;
#pragma unroll
        for (int i = 0; i < 16; i++) dst[i] = o0[i];
#pragma unroll
        for (int i = 0; i < 8; i++) dst[16 + i] = sA[i];
#pragma unroll
        for (int i = 0; i < 24; i++) dst[24 + i] = qA[i];
    }
    __syncthreads();
    if (cg == 0) {
        const float* src = red + half_id * 48;
#pragma unroll
        for (int i = 0; i < 16; i++) o0[i] += src[i];
#pragma unroll
        for (int i = 0; i < 8; i++) sA[i] += src[16 + i];
#pragma unroll
        for (int i = 0; i < 24; i++) qA[i] += src[24 + i];

        // ---- epilogue ----
        const float c011 = 0.125f;                 // pw011/sqrt(3)
        const float c101 = 0.17677669529663687f;   // pw101/sqrt(3)
#pragma unroll
        for (int rh = 0; rh < 2; rh++) {
            const int row = rbase + rh * 8;
            float* orow = out + row * 80;
            const int s = rh * 4;
#pragma unroll
            for (int jm = 0; jm < 4; jm++) {
                orow[8 * jm + q2]     = o0[(s + jm) * 2];
                orow[8 * jm + q2 + 1] = o0[(s + jm) * 2 + 1];
            }
            const float x20  = fea_in2[row * 4 + 0];
            const float x21a = fea_in2[row * 4 + 1];
            const float x21b = fea_in2[row * 4 + 2];
            const float x21c = fea_in2[row * 4 + 3];
#pragma unroll
            for (int slot = 0; slot < 4; slot++) {
                const int w = 8 * (slot >> 1) + q2 + (slot & 1);
                const float sv = sA[s + slot];
                orow[32 + 3 * w + 0] = c011 * x21a * sv + c101 * x20 * qA[(s + slot) * 3 + 0];
                orow[32 + 3 * w + 1] = c011 * x21b * sv + c101 * x20 * qA[(s + slot) * 3 + 1];
                orow[32 + 3 * w + 2] = c011 * x21c * sv + c101 * x20 * qA[(s + slot) * 3 + 2];
            }
        }
    }
}

// ---------------------------------------------------------------------------
extern "C" void kernel_launch(void* const* d_in, const int* in_sizes, int n_in,
                              void* d_out, int out_size)
{
    const float* fea_in1    = (const float*)d_in[0];
    const float* fea_in2    = (const float*)d_in[1];
    const float* fea_weight = (const float*)d_in[2];
    const float* W1         = (const float*)d_in[3];
    const float* W2         = (const float*)d_in[4];
    float* out = (float*)d_out;

    cudaFuncSetAttribute(k2_main, cudaFuncAttributeMaxDynamicSharedMemorySize, SMEM_TOTAL);

    k0_prepB<<<576, 256>>>(W2, W1);
    k2_main<<<E_ROWS / TILE_R, 256, SMEM_TOTAL>>>(fea_in1, fea_in2, fea_weight, out);
}